// round 15
// baseline (speedup 1.0000x reference)
#include <cuda_runtime.h>
#include <cuda_fp16.h>
#include <mma.h>
#include <math.h>

using namespace nvcuda;

// ---------------------------------------------------------------------------
// Problem constants
// ---------------------------------------------------------------------------
#define MAXN   50000
#define DEGCAP 64
#define INDIM  128
#define HID    32
#define H1     4
#define C1     128
#define CW     144          // 128 h1 cols + 4 as + 4 ad + 8 pad
#define AGENTS 32
#define NEG    0.2f

// packed f32x2 ops (sm_103a)
#define FMA2(acc, a, b) \
    asm("fma.rn.f32x2 %0, %1, %2, %0;" : "+l"(acc) : "l"(a), "l"(b))
#define PACK2(out, lo, hi) \
    asm("mov.b64 %0, {%1, %2};" : "=l"(out) : "f"(lo), "f"(hi))
#define UNPACK2(lo, hi, in) \
    asm("mov.b64 {%0, %1}, %2;" : "=f"(lo), "=f"(hi) : "l"(in))

// ---------------------------------------------------------------------------
// Device scratch
// ---------------------------------------------------------------------------
__device__ __align__(16) __half g_h1h[MAXN * C1];   // layer1 feats (fp16)
__device__ __align__(16) __half g_Wch[INDIM * CW];  // W1|Ws|Wd fp16
__device__ __align__(16) float g_x1 [MAXN * C1];    // layer1 out (biased+elu)
__device__ __align__(16) float g_as1[MAXN * H1];
__device__ __align__(16) float g_ad1[MAXN * H1];
__device__ __align__(16) __half g_h2h[MAXN * HID];  // layer2 feats (fp16)
__device__ __align__(16) float g_o2 [MAXN * HID];
__device__ float g_ws2[INDIM];
__device__ float g_wd2[INDIM];
__device__ __align__(16) float g_as2b[MAXN * 4];    // as2 padded to stride 4
__device__ float g_ad2[MAXN];
__device__ int   g_cnt[MAXN];
__device__ int   g_csr[MAXN * DEGCAP];              // stores src*4 (scaled)
__device__ int   g_is64;

// ---------------------------------------------------------------------------
// Helpers
// ---------------------------------------------------------------------------
__device__ __forceinline__ float lrelu(float v) { return fmaxf(v, NEG * v); }
__device__ __forceinline__ float elu(float v)   { return v > 0.f ? v : expm1f(v); }

// ---------------------------------------------------------------------------
// prep: zero counters, probe dtype, zero value cell
// ---------------------------------------------------------------------------
__global__ void prep_kernel(const unsigned int* __restrict__ w,
                            float* __restrict__ out, int Nn) {
    int i = blockIdx.x * blockDim.x + threadIdx.x;
    if (i < Nn) g_cnt[i] = 0;
    if (i == 0) {
        out[(long long)AGENTS * Nn] = 0.f;
        int allz = 1;
        for (int k = 0; k < 16; k++)
            if (w[2 * k + 1] != 0u) allz = 0;
        g_is64 = allz;
    }
}

// ---------------------------------------------------------------------------
// cvt: build folded weights (W1|Ws|Wd fp16; ws2/wd2 fp32)
// ---------------------------------------------------------------------------
__global__ void cvt_kernel(const float* __restrict__ W1,
                           const float* __restrict__ a1s,
                           const float* __restrict__ a1d,
                           const float* __restrict__ W2,
                           const float* __restrict__ a2s,
                           const float* __restrict__ a2d) {
    int gid = blockIdx.x * blockDim.x + threadIdx.x;
    if (gid < INDIM * C1) {
        int k = gid >> 7, c = gid & 127;
        g_Wch[k * CW + c] = __float2half_rn(W1[k * C1 + c]);
    } else if (gid < INDIM * C1 + INDIM * 16) {
        int i = gid - INDIM * C1;
        int k = i >> 4, cc = i & 15;
        float v = 0.f;
        if (cc < 4) {
            for (int j = 0; j < HID; j++)
                v += W1[k * C1 + cc * HID + j] * a1s[cc * HID + j];
        } else if (cc < 8) {
            int h = cc - 4;
            for (int j = 0; j < HID; j++)
                v += W1[k * C1 + h * HID + j] * a1d[h * HID + j];
        }
        g_Wch[k * CW + 128 + cc] = __float2half_rn(v);
    } else if (gid < INDIM * C1 + INDIM * 16 + 2 * INDIM) {
        int i = gid - INDIM * C1 - INDIM * 16;
        int k = i >> 1;
        const float* av = (i & 1) ? a2d : a2s;
        float v = 0.f;
        for (int j = 0; j < HID; j++) v += W2[k * HID + j] * av[j];
        if (i & 1) g_wd2[k] = v; else g_ws2[k] = v;
    }
}

// ---------------------------------------------------------------------------
// Scatter: padded-CSR bump allocation; 4 consecutive edges/thread,
// vectorized index loads; stores src*4 (scaled).  4th launch → profiled.
// ---------------------------------------------------------------------------
__global__ void scatter_kernel(const void* __restrict__ ei, int E, int etot) {
    int i0 = (blockIdx.x * blockDim.x + threadIdx.x) * 4;
    if (i0 >= etot) return;
    int s[4], d[4];
    if (g_is64) {
        const longlong2* ps = (const longlong2*)ei;
        const longlong2* pd = (const longlong2*)((const long long*)ei + E);
        if (i0 + 3 < E) {
            longlong2 a = ps[i0 >> 1], b = ps[(i0 >> 1) + 1];
            longlong2 c = pd[i0 >> 1], e2 = pd[(i0 >> 1) + 1];
            s[0] = (int)a.x; s[1] = (int)a.y; s[2] = (int)b.x; s[3] = (int)b.y;
            d[0] = (int)c.x; d[1] = (int)c.y; d[2] = (int)e2.x; d[3] = (int)e2.y;
        } else {
            const long long* q = (const long long*)ei;
#pragma unroll
            for (int k = 0; k < 4; k++) {
                int i = i0 + k;
                if (i < E) { s[k] = (int)q[i]; d[k] = (int)q[E + i]; }
                else       { s[k] = i - E;     d[k] = i - E; }
            }
        }
    } else {
        const int4* ps = (const int4*)ei;
        const int4* pd = (const int4*)((const int*)ei + E);
        if (i0 + 3 < E && (E & 3) == 0) {
            int4 a = ps[i0 >> 2], c = pd[i0 >> 2];
            s[0] = a.x; s[1] = a.y; s[2] = a.z; s[3] = a.w;
            d[0] = c.x; d[1] = c.y; d[2] = c.z; d[3] = c.w;
        } else {
            const int* q = (const int*)ei;
#pragma unroll
            for (int k = 0; k < 4; k++) {
                int i = i0 + k;
                if (i < E) { s[k] = q[i]; d[k] = q[E + i]; }
                else       { s[k] = i - E; d[k] = i - E; }
            }
        }
    }
#pragma unroll
    for (int k = 0; k < 4; k++) {
        int i = i0 + k;
        if (i < etot) {
            int pos = atomicAdd(&g_cnt[d[k]], 1);
            g_csr[d[k] * DEGCAP + pos] = s[k] * 4;
        }
    }
}

// ---------------------------------------------------------------------------
// GEMM1 tensor cores: [32 nodes] x [144 cols], 9 warps.
// v2: W staged in smem (coalesced) then LDSM; epilogue sbuf ALIASES the W
// region (W dead after fragment loads) to fit 48KB static smem.
// ---------------------------------------------------------------------------
__global__ __launch_bounds__(288) void gemm1_kernel(
    const float* __restrict__ x, int Nn) {
    __shared__ __half xh[32][136];
    __shared__ __align__(16) char uni[INDIM * CW * 2];  // W(fp16) / sbuf(fp32)
    __half* Wsm = (__half*)uni;
    float (*sbuf)[148] = (float (*)[148])uni;
    int t  = threadIdx.x;
    int n0 = blockIdx.x * 32;

    // load x tile -> fp16 smem
    const float4* xv = (const float4*)x;
    for (int i = t; i < 32 * 32; i += 288) {
        int m = i >> 5, c4 = i & 31;
        int n = n0 + m;
        float4 v = (n < Nn) ? xv[(long long)n * 32 + c4]
                            : make_float4(0.f, 0.f, 0.f, 0.f);
        __half2* dst = (__half2*)&xh[m][c4 * 4];
        dst[0] = __floats2half2_rn(v.x, v.y);
        dst[1] = __floats2half2_rn(v.z, v.w);
    }
    // stage W (coalesced float4): 128*144 halfs = 2304 float4
    {
        const float4* wv = (const float4*)g_Wch;
        float4* wd = (float4*)Wsm;
        for (int i = t; i < (INDIM * CW * 2) / 16; i += 288) wd[i] = wv[i];
    }
    __syncthreads();

    int w = t >> 5;

    wmma::fragment<wmma::matrix_b, 16, 16, 16, __half, wmma::row_major> b[8];
#pragma unroll
    for (int k8 = 0; k8 < 8; k8++)
        wmma::load_matrix_sync(b[k8], Wsm + (k8 * 16) * CW + w * 16, CW);
    __syncthreads();   // all LDSM done before sbuf overwrites W region

    wmma::fragment<wmma::accumulator, 16, 16, 16, float> cf[2];
#pragma unroll
    for (int ng = 0; ng < 2; ng++) {
        wmma::fill_fragment(cf[ng], 0.f);
#pragma unroll
        for (int k8 = 0; k8 < 8; k8++) {
            wmma::fragment<wmma::matrix_a, 16, 16, 16, __half, wmma::row_major> a;
            wmma::load_matrix_sync(a, &xh[ng * 16][k8 * 16], 136);
            wmma::mma_sync(cf[ng], a, b[k8], cf[ng]);
        }
        wmma::store_matrix_sync(&sbuf[ng * 16][w * 16], cf[ng], 148,
                                wmma::mem_row_major);
    }
    __syncthreads();

    for (int i = t; i < 32 * 64; i += 288) {
        int n = i >> 6, cp = i & 63;
        int gn = n0 + n;
        if (gn < Nn) {
            __half2 hv = __floats2half2_rn(sbuf[n][cp * 2], sbuf[n][cp * 2 + 1]);
            ((__half2*)g_h1h)[(long long)gn * 64 + cp] = hv;
        }
    }
    if (t < 256) {
        int n = t >> 3, q = t & 7;
        int gn = n0 + n;
        if (gn < Nn) {
            if (q < 4) g_as1[gn * H1 + q]       = sbuf[n][128 + q];
            else       g_ad1[gn * H1 + (q - 4)] = sbuf[n][132 + (q - 4)];
        }
    }
}

// ---------------------------------------------------------------------------
// Layer1 attention, staging-free, scaled csr (unchanged from R14).
// ---------------------------------------------------------------------------
__global__ __launch_bounds__(256, 6) void attn1_kernel(
    const float* __restrict__ b1, int Nn) {
    int warp = (blockIdx.x * blockDim.x + threadIdx.x) >> 5;
    int lane = threadIdx.x & 31;
    if (warp >= Nn) return;
    int start = warp * DEGCAP;
    int deg   = g_cnt[warp];
    int lane16 = lane & 15;
    int ep     = lane >> 4;
    int hh     = lane16 >> 2;
    float adh  = g_ad1[warp * H1 + hh];

    float den = 0.f;
    float acc[8];
#pragma unroll
    for (int i = 0; i < 8; i++) acc[i] = 0.f;
    const uint4* h1 = (const uint4*)g_h1h;
    const __half2 hz = __float2half2_rn(0.f);

    for (int base = 0; base < deg; base += 8) {
        __half2 t0 = hz, t1 = hz, t2 = hz, t3 = hz;
#pragma unroll
        for (int jj = 0; jj < 8; jj += 2) {
            int e = base + jj + ep;
            bool ok = e < deg;
            int s4 = ok ? __ldg(&g_csr[start + e]) : 0;     // src*4
            float va = __ldg(&g_as1[s4 + hh]);
            float num = ok ? __expf(lrelu(va + adh)) : 0.f;
            den += num;
            __half2 nh = __float2half2_rn(num);
            uint4 u = h1[(s4 << 2) + lane16];
            t0 = __hfma2(*(__half2*)&u.x, nh, t0);
            t1 = __hfma2(*(__half2*)&u.y, nh, t1);
            t2 = __hfma2(*(__half2*)&u.z, nh, t2);
            t3 = __hfma2(*(__half2*)&u.w, nh, t3);
        }
        float2 q;
        q = __half22float2(t0); acc[0] += q.x; acc[1] += q.y;
        q = __half22float2(t1); acc[2] += q.x; acc[3] += q.y;
        q = __half22float2(t2); acc[4] += q.x; acc[5] += q.y;
        q = __half22float2(t3); acc[6] += q.x; acc[7] += q.y;
    }

    den += __shfl_xor_sync(0xffffffffu, den, 16);
#pragma unroll
    for (int i = 0; i < 8; i++)
        acc[i] += __shfl_xor_sync(0xffffffffu, acc[i], 16);

    if (lane < 16) {
        float rden = 1.f / den;
        const float4* bb = (const float4*)(b1 + lane16 * 8);
        float4 b0 = bb[0], b1v = bb[1];
        float4 o0, o1;
        o0.x = elu(acc[0] * rden + b0.x);  o0.y = elu(acc[1] * rden + b0.y);
        o0.z = elu(acc[2] * rden + b0.z);  o0.w = elu(acc[3] * rden + b0.w);
        o1.x = elu(acc[4] * rden + b1v.x); o1.y = elu(acc[5] * rden + b1v.y);
        o1.z = elu(acc[6] * rden + b1v.z); o1.w = elu(acc[7] * rden + b1v.w);
        float4* dst = (float4*)(g_x1 + (long long)warp * C1 + lane16 * 8);
        dst[0] = o0; dst[1] = o1;
    }
}

// ---------------------------------------------------------------------------
// GEMM2 (fp32 FFMA2) + folded as2/ad2; as2 written at stride 4.
// ---------------------------------------------------------------------------
__global__ __launch_bounds__(128) void gemm2_kernel(
    const float* __restrict__ W2, int Nn) {
    __shared__ float xs[32][132];
    int t = threadIdx.x;
    int g = t >> 5;
    int c = t & 31;
    int n0 = blockIdx.x * 32;

    const float4* xv = (const float4*)g_x1;
    for (int i = t; i < 32 * 32; i += 128) {
        int m = i >> 5, cc = i & 31;
        int n = n0 + m;
        float4 v = (n < Nn) ? xv[(long long)n * 32 + cc]
                            : make_float4(0.f, 0.f, 0.f, 0.f);
        *(float4*)&xs[m][cc * 4] = v;
    }
    __syncthreads();

    unsigned long long acc[8];
#pragma unroll
    for (int m = 0; m < 8; m++) acc[m] = 0ull;

    for (int kt = 0; kt < C1; kt += 8) {
        float w[8];
#pragma unroll
        for (int j = 0; j < 8; j++) w[j] = W2[(kt + j) * HID + c];
        unsigned long long wp0, wp1, wp2, wp3;
        PACK2(wp0, w[0], w[1]);
        PACK2(wp1, w[2], w[3]);
        PACK2(wp2, w[4], w[5]);
        PACK2(wp3, w[6], w[7]);
#pragma unroll
        for (int m = 0; m < 8; m++) {
            const float4* xr = (const float4*)&xs[g * 8 + m][kt];
            float4 xa = xr[0], xb = xr[1];
            FMA2(acc[m], *(unsigned long long*)&xa.x, wp0);
            FMA2(acc[m], *(unsigned long long*)&xa.z, wp1);
            FMA2(acc[m], *(unsigned long long*)&xb.x, wp2);
            FMA2(acc[m], *(unsigned long long*)&xb.z, wp3);
        }
    }

#pragma unroll
    for (int m = 0; m < 8; m++) {
        float lo, hi;
        UNPACK2(lo, hi, acc[m]);
        float a = lo + hi;
        int n = n0 + g * 8 + m;
        if (n < Nn) g_h2h[(long long)n * HID + c] = __float2half_rn(a);
    }

    int mq = c >> 2, p = c & 3;
    int node = g * 8 + mq, gn2 = n0 + node;
    float s2 = 0.f, d2 = 0.f;
#pragma unroll
    for (int j = 0; j < 32; j++) {
        int k = p + j * 4;
        float xv2 = xs[node][k];
        s2 += xv2 * g_ws2[k];
        d2 += xv2 * g_wd2[k];
    }
    s2 += __shfl_xor_sync(0xffffffffu, s2, 1);
    s2 += __shfl_xor_sync(0xffffffffu, s2, 2);
    d2 += __shfl_xor_sync(0xffffffffu, d2, 1);
    d2 += __shfl_xor_sync(0xffffffffu, d2, 2);
    if (p == 0 && gn2 < Nn) { g_as2b[gn2 * 4] = s2; g_ad2[gn2] = d2; }
}

// ---------------------------------------------------------------------------
// Layer2 attention, STAGED (1 head: one exp per edge), scaled csr.
// ---------------------------------------------------------------------------
__global__ __launch_bounds__(256) void attn2_kernel(
    const float* __restrict__ b2, int Nn) {
    __shared__ __half2 s_al[8][32];
    __shared__ int     s_src[8][32];
    int wg   = threadIdx.x >> 5;
    int warp = (blockIdx.x * blockDim.x + threadIdx.x) >> 5;
    int lane = threadIdx.x & 31;
    if (warp >= Nn) return;
    int start = warp * DEGCAP;
    int deg   = g_cnt[warp];
    float adn = g_ad2[warp];
    int lane16 = lane & 15;
    int ep     = lane >> 4;

    float den = 0.f, ax = 0.f, ay = 0.f;
    const __half2* h2 = (const __half2*)g_h2h;
    const __half2 hz = __float2half2_rn(0.f);

#define A2_BODY(jj)                                                        \
    do {                                                                   \
        int ea = (jj) + ep, eb = (jj) + 2 + ep;                            \
        int sa = s_src[wg][ea], sb = s_src[wg][eb];                        \
        __half2 ala = s_al[wg][ea], alb = s_al[wg][eb];                    \
        t = __hfma2(h2[(sa << 2) + lane16], ala, t);                       \
        t = __hfma2(h2[(sb << 2) + lane16], alb, t);                       \
    } while (0)

    for (int base = 0; base < deg; base += 32) {
        int cnt = min(32, deg - base);
        int s4 = 0; float num = 0.f;
        if (lane < cnt) {
            s4 = g_csr[start + base + lane];
            num = __expf(lrelu(__ldg(&g_as2b[s4]) + adn));
            den += num;
        }
        s_src[wg][lane] = s4;
        s_al[wg][lane]  = __float2half2_rn(num);
        __syncwarp();

        int cnt4 = (cnt + 3) & ~3;
        int j = 0;
        for (; j + 8 <= cnt4; j += 8) {
            __half2 t = hz;
            A2_BODY(j);
            A2_BODY(j + 4);
            float2 q = __half22float2(t);
            ax += q.x; ay += q.y;
        }
        if (j < cnt4) {
            __half2 t = hz;
            A2_BODY(j);
            float2 q = __half22float2(t);
            ax += q.x; ay += q.y;
        }
        __syncwarp();
    }
#pragma unroll
    for (int off = 16; off; off >>= 1)
        den += __shfl_xor_sync(0xffffffffu, den, off);
    ax += __shfl_xor_sync(0xffffffffu, ax, 16);
    ay += __shfl_xor_sync(0xffffffffu, ay, 16);

    if (lane < 16) {
        float rden = 1.f / den;
        float2 bb = ((const float2*)b2)[lane16];
        float2 o;
        o.x = elu(ax * rden + bb.x);
        o.y = elu(ay * rden + bb.y);
        ((float2*)g_o2)[warp * 16 + lane16] = o;
    }
}

// ---------------------------------------------------------------------------
// Actor/critic heads.
// ---------------------------------------------------------------------------
__global__ __launch_bounds__(1024) void heads_kernel(
    const float* __restrict__ Wa, const float* __restrict__ ba,
    const float* __restrict__ Wc, const float* __restrict__ bc,
    float* __restrict__ out, int Nn) {
    __shared__ float Was[AGENTS * HID];
    __shared__ float tile[32][33];
    __shared__ float warr[32];
    int t = threadIdx.x;
    Was[t & (AGENTS * HID - 1)] = Wa[t & (AGENTS * HID - 1)];
    __syncthreads();

    int w = t >> 5, lane = t & 31;
    int n = blockIdx.x * 32 + w;
    float hv = (n < Nn) ? g_o2[(long long)n * HID + lane] : 0.f;

    float acc = 0.f;
    float vs = hv * Wc[lane];
#pragma unroll
    for (int f = 0; f < HID; f++) {
        float xv = __shfl_sync(0xffffffffu, hv, f);
        acc += xv * Was[f * AGENTS + lane];
    }
    tile[w][lane] = acc + ba[lane];
#pragma unroll
    for (int off = 16; off; off >>= 1) vs += __shfl_down_sync(0xffffffffu, vs, off);
    if (lane == 0) warr[w] = vs;
    __syncthreads();

    int n2 = blockIdx.x * 32 + lane;
    if (n2 < Nn) out[(long long)w * Nn + n2] = tile[lane][w];

    if (t == 0) {
        float bs = 0.f;
#pragma unroll
        for (int i = 0; i < 32; i++) bs += warr[i];
        atomicAdd(out + (long long)AGENTS * Nn, bs / (float)Nn);
        if (blockIdx.x == 0) atomicAdd(out + (long long)AGENTS * Nn, bc[0]);
    }
}

// ---------------------------------------------------------------------------
// Launch: scatter in the 4th (profiled) slot this round.
// Deps: prep->scatter; cvt->gemm1; gemm1+scatter->attn1 -> gemm2 -> attn2.
// ---------------------------------------------------------------------------
extern "C" void kernel_launch(void* const* d_in, const int* in_sizes, int n_in,
                              void* d_out, int out_size) {
    const float* x   = (const float*)d_in[0];
    const void*  ei  = d_in[1];
    const float* W1  = (const float*)d_in[2];
    const float* a1s = (const float*)d_in[3];
    const float* a1d = (const float*)d_in[4];
    const float* b1  = (const float*)d_in[5];
    const float* W2  = (const float*)d_in[6];
    const float* a2s = (const float*)d_in[7];
    const float* a2d = (const float*)d_in[8];
    const float* b2  = (const float*)d_in[9];
    const float* Wa  = (const float*)d_in[10];
    const float* ba  = (const float*)d_in[11];
    const float* Wc  = (const float*)d_in[12];
    const float* bc  = (const float*)d_in[13];
    float* out = (float*)d_out;

    int Nn   = in_sizes[0] / INDIM;
    int E    = in_sizes[1] / 2;
    int etot = E + Nn;
    int ncvt = INDIM * C1 + INDIM * 16 + 2 * INDIM;

    prep_kernel<<<(Nn + 255) / 256, 256>>>((const unsigned int*)ei, out, Nn);
    cvt_kernel<<<(ncvt + 255) / 256, 256>>>(W1, a1s, a1d, W2, a2s, a2d);
    gemm1_kernel<<<(Nn + 31) / 32, 288>>>(x, Nn);
    scatter_kernel<<<(etot + 1023) / 1024, 256>>>(ei, E, etot); // 4th: profiled

    attn1_kernel<<<(Nn * 32 + 255) / 256, 256>>>(b1, Nn);
    gemm2_kernel<<<(Nn + 31) / 32, 128>>>(W2, Nn);
    attn2_kernel<<<(Nn * 32 + 255) / 256, 256>>>(b2, Nn);
    heads_kernel<<<(Nn + 31) / 32, 1024>>>(Wa, ba, Wc, bc, out, Nn);
}

// round 16
// speedup vs baseline: 1.0071x; 1.0071x over previous
#include <cuda_runtime.h>
#include <cuda_fp16.h>
#include <mma.h>
#include <math.h>

using namespace nvcuda;

// ---------------------------------------------------------------------------
// Problem constants
// ---------------------------------------------------------------------------
#define MAXN   50000
#define DEGCAP 64
#define INDIM  128
#define HID    32
#define H1     4
#define C1     128
#define CW     144          // 128 h1 cols + 4 as + 4 ad + 8 pad
#define AGENTS 32
#define NEG    0.2f

// packed f32x2 ops (sm_103a)
#define FMA2(acc, a, b) \
    asm("fma.rn.f32x2 %0, %1, %2, %0;" : "+l"(acc) : "l"(a), "l"(b))
#define PACK2(out, lo, hi) \
    asm("mov.b64 %0, {%1, %2};" : "=l"(out) : "f"(lo), "f"(hi))
#define UNPACK2(lo, hi, in) \
    asm("mov.b64 {%0, %1}, %2;" : "=f"(lo), "=f"(hi) : "l"(in))

// ---------------------------------------------------------------------------
// Device scratch
// ---------------------------------------------------------------------------
__device__ __align__(16) __half g_h1h[MAXN * C1];   // layer1 feats (fp16)
__device__ __align__(16) __half g_Wch[INDIM * CW];  // W1|Ws|Wd fp16
__device__ __align__(16) float g_x1 [MAXN * C1];    // layer1 out (biased+elu)
__device__ __align__(16) float g_as1[MAXN * H1];
__device__ __align__(16) float g_ad1[MAXN * H1];
__device__ __align__(16) __half g_h2h[MAXN * HID];  // layer2 feats (fp16)
__device__ __align__(16) float g_o2 [MAXN * HID];
__device__ float g_ws2[INDIM];
__device__ float g_wd2[INDIM];
__device__ __align__(16) float g_as2b[MAXN * 4];    // as2 padded to stride 4
__device__ float g_ad2[MAXN];
__device__ int   g_cnt[MAXN];
__device__ int   g_csr[MAXN * DEGCAP];              // stores src*4 (scaled)
__device__ int   g_is64;

// ---------------------------------------------------------------------------
// Helpers
// ---------------------------------------------------------------------------
__device__ __forceinline__ float lrelu(float v) { return fmaxf(v, NEG * v); }
__device__ __forceinline__ float elu(float v)   { return v > 0.f ? v : expm1f(v); }

// ---------------------------------------------------------------------------
// prep: zero counters, probe dtype, zero value cell
// ---------------------------------------------------------------------------
__global__ void prep_kernel(const unsigned int* __restrict__ w,
                            float* __restrict__ out, int Nn) {
    int i = blockIdx.x * blockDim.x + threadIdx.x;
    if (i < Nn) g_cnt[i] = 0;
    if (i == 0) {
        out[(long long)AGENTS * Nn] = 0.f;
        int allz = 1;
        for (int k = 0; k < 16; k++)
            if (w[2 * k + 1] != 0u) allz = 0;
        g_is64 = allz;
    }
}

// ---------------------------------------------------------------------------
// cvt: build folded weights (W1|Ws|Wd fp16; ws2/wd2 fp32)
// ---------------------------------------------------------------------------
__global__ void cvt_kernel(const float* __restrict__ W1,
                           const float* __restrict__ a1s,
                           const float* __restrict__ a1d,
                           const float* __restrict__ W2,
                           const float* __restrict__ a2s,
                           const float* __restrict__ a2d) {
    int gid = blockIdx.x * blockDim.x + threadIdx.x;
    if (gid < INDIM * C1) {
        int k = gid >> 7, c = gid & 127;
        g_Wch[k * CW + c] = __float2half_rn(W1[k * C1 + c]);
    } else if (gid < INDIM * C1 + INDIM * 16) {
        int i = gid - INDIM * C1;
        int k = i >> 4, cc = i & 15;
        float v = 0.f;
        if (cc < 4) {
            for (int j = 0; j < HID; j++)
                v += W1[k * C1 + cc * HID + j] * a1s[cc * HID + j];
        } else if (cc < 8) {
            int h = cc - 4;
            for (int j = 0; j < HID; j++)
                v += W1[k * C1 + h * HID + j] * a1d[h * HID + j];
        }
        g_Wch[k * CW + 128 + cc] = __float2half_rn(v);
    } else if (gid < INDIM * C1 + INDIM * 16 + 2 * INDIM) {
        int i = gid - INDIM * C1 - INDIM * 16;
        int k = i >> 1;
        const float* av = (i & 1) ? a2d : a2s;
        float v = 0.f;
        for (int j = 0; j < HID; j++) v += W2[k * HID + j] * av[j];
        if (i & 1) g_wd2[k] = v; else g_ws2[k] = v;
    }
}

// ---------------------------------------------------------------------------
// Scatter: padded-CSR bump allocation; 4 consecutive edges/thread,
// vectorized index loads; stores src*4 (scaled).
// ---------------------------------------------------------------------------
__global__ void scatter_kernel(const void* __restrict__ ei, int E, int etot) {
    int i0 = (blockIdx.x * blockDim.x + threadIdx.x) * 4;
    if (i0 >= etot) return;
    int s[4], d[4];
    if (g_is64) {
        const longlong2* ps = (const longlong2*)ei;
        const longlong2* pd = (const longlong2*)((const long long*)ei + E);
        if (i0 + 3 < E) {
            longlong2 a = ps[i0 >> 1], b = ps[(i0 >> 1) + 1];
            longlong2 c = pd[i0 >> 1], e2 = pd[(i0 >> 1) + 1];
            s[0] = (int)a.x; s[1] = (int)a.y; s[2] = (int)b.x; s[3] = (int)b.y;
            d[0] = (int)c.x; d[1] = (int)c.y; d[2] = (int)e2.x; d[3] = (int)e2.y;
        } else {
            const long long* q = (const long long*)ei;
#pragma unroll
            for (int k = 0; k < 4; k++) {
                int i = i0 + k;
                if (i < E) { s[k] = (int)q[i]; d[k] = (int)q[E + i]; }
                else       { s[k] = i - E;     d[k] = i - E; }
            }
        }
    } else {
        const int4* ps = (const int4*)ei;
        const int4* pd = (const int4*)((const int*)ei + E);
        if (i0 + 3 < E && (E & 3) == 0) {
            int4 a = ps[i0 >> 2], c = pd[i0 >> 2];
            s[0] = a.x; s[1] = a.y; s[2] = a.z; s[3] = a.w;
            d[0] = c.x; d[1] = c.y; d[2] = c.z; d[3] = c.w;
        } else {
            const int* q = (const int*)ei;
#pragma unroll
            for (int k = 0; k < 4; k++) {
                int i = i0 + k;
                if (i < E) { s[k] = q[i]; d[k] = q[E + i]; }
                else       { s[k] = i - E; d[k] = i - E; }
            }
        }
    }
#pragma unroll
    for (int k = 0; k < 4; k++) {
        int i = i0 + k;
        if (i < etot) {
            int pos = atomicAdd(&g_cnt[d[k]], 1);
            g_csr[d[k] * DEGCAP + pos] = s[k] * 4;
        }
    }
}

// ---------------------------------------------------------------------------
// GEMM1 tensor cores (R14 v1, proven 22.3us): [32 nodes] x [144 cols],
// 9 warps, B fragments loaded directly from global, folded as/ad cols.
// ---------------------------------------------------------------------------
__global__ __launch_bounds__(288) void gemm1_kernel(
    const float* __restrict__ x, int Nn) {
    __shared__ __half xh[32][136];
    __shared__ float  sbuf[32][148];
    int t  = threadIdx.x;
    int n0 = blockIdx.x * 32;

    const float4* xv = (const float4*)x;
    for (int i = t; i < 32 * 32; i += 288) {
        int m = i >> 5, c4 = i & 31;
        int n = n0 + m;
        float4 v = (n < Nn) ? xv[(long long)n * 32 + c4]
                            : make_float4(0.f, 0.f, 0.f, 0.f);
        __half2* dst = (__half2*)&xh[m][c4 * 4];
        dst[0] = __floats2half2_rn(v.x, v.y);
        dst[1] = __floats2half2_rn(v.z, v.w);
    }
    __syncthreads();

    int w = t >> 5;

    wmma::fragment<wmma::matrix_b, 16, 16, 16, __half, wmma::row_major> b[8];
#pragma unroll
    for (int k8 = 0; k8 < 8; k8++)
        wmma::load_matrix_sync(b[k8], g_Wch + (k8 * 16) * CW + w * 16, CW);

#pragma unroll
    for (int ng = 0; ng < 2; ng++) {
        wmma::fragment<wmma::accumulator, 16, 16, 16, float> cf;
        wmma::fill_fragment(cf, 0.f);
#pragma unroll
        for (int k8 = 0; k8 < 8; k8++) {
            wmma::fragment<wmma::matrix_a, 16, 16, 16, __half, wmma::row_major> a;
            wmma::load_matrix_sync(a, &xh[ng * 16][k8 * 16], 136);
            wmma::mma_sync(cf, a, b[k8], cf);
        }
        wmma::store_matrix_sync(&sbuf[ng * 16][w * 16], cf, 148,
                                wmma::mem_row_major);
    }
    __syncthreads();

    for (int i = t; i < 32 * 64; i += 288) {
        int n = i >> 6, cp = i & 63;
        int gn = n0 + n;
        if (gn < Nn) {
            __half2 hv = __floats2half2_rn(sbuf[n][cp * 2], sbuf[n][cp * 2 + 1]);
            ((__half2*)g_h1h)[(long long)gn * 64 + cp] = hv;
        }
    }
    if (t < 256) {
        int n = t >> 3, q = t & 7;
        int gn = n0 + n;
        if (gn < Nn) {
            if (q < 4) g_as1[gn * H1 + q]       = sbuf[n][128 + q];
            else       g_ad1[gn * H1 + (q - 4)] = sbuf[n][132 + (q - 4)];
        }
    }
}

// ---------------------------------------------------------------------------
// Layer1 attention, staging-free, scaled csr.
// ---------------------------------------------------------------------------
__global__ __launch_bounds__(256, 6) void attn1_kernel(
    const float* __restrict__ b1, int Nn) {
    int warp = (blockIdx.x * blockDim.x + threadIdx.x) >> 5;
    int lane = threadIdx.x & 31;
    if (warp >= Nn) return;
    int start = warp * DEGCAP;
    int deg   = g_cnt[warp];
    int lane16 = lane & 15;
    int ep     = lane >> 4;
    int hh     = lane16 >> 2;
    float adh  = g_ad1[warp * H1 + hh];

    float den = 0.f;
    float acc[8];
#pragma unroll
    for (int i = 0; i < 8; i++) acc[i] = 0.f;
    const uint4* h1 = (const uint4*)g_h1h;
    const __half2 hz = __float2half2_rn(0.f);

    for (int base = 0; base < deg; base += 8) {
        __half2 t0 = hz, t1 = hz, t2 = hz, t3 = hz;
#pragma unroll
        for (int jj = 0; jj < 8; jj += 2) {
            int e = base + jj + ep;
            bool ok = e < deg;
            int s4 = ok ? __ldg(&g_csr[start + e]) : 0;     // src*4
            float va = __ldg(&g_as1[s4 + hh]);
            float num = ok ? __expf(lrelu(va + adh)) : 0.f;
            den += num;
            __half2 nh = __float2half2_rn(num);
            uint4 u = h1[(s4 << 2) + lane16];
            t0 = __hfma2(*(__half2*)&u.x, nh, t0);
            t1 = __hfma2(*(__half2*)&u.y, nh, t1);
            t2 = __hfma2(*(__half2*)&u.z, nh, t2);
            t3 = __hfma2(*(__half2*)&u.w, nh, t3);
        }
        float2 q;
        q = __half22float2(t0); acc[0] += q.x; acc[1] += q.y;
        q = __half22float2(t1); acc[2] += q.x; acc[3] += q.y;
        q = __half22float2(t2); acc[4] += q.x; acc[5] += q.y;
        q = __half22float2(t3); acc[6] += q.x; acc[7] += q.y;
    }

    den += __shfl_xor_sync(0xffffffffu, den, 16);
#pragma unroll
    for (int i = 0; i < 8; i++)
        acc[i] += __shfl_xor_sync(0xffffffffu, acc[i], 16);

    if (lane < 16) {
        float rden = 1.f / den;
        const float4* bb = (const float4*)(b1 + lane16 * 8);
        float4 b0 = bb[0], b1v = bb[1];
        float4 o0, o1;
        o0.x = elu(acc[0] * rden + b0.x);  o0.y = elu(acc[1] * rden + b0.y);
        o0.z = elu(acc[2] * rden + b0.z);  o0.w = elu(acc[3] * rden + b0.w);
        o1.x = elu(acc[4] * rden + b1v.x); o1.y = elu(acc[5] * rden + b1v.y);
        o1.z = elu(acc[6] * rden + b1v.z); o1.w = elu(acc[7] * rden + b1v.w);
        float4* dst = (float4*)(g_x1 + (long long)warp * C1 + lane16 * 8);
        dst[0] = o0; dst[1] = o1;
    }
}

// ---------------------------------------------------------------------------
// GEMM2 (fp32 FFMA2) + folded as2/ad2; as2 written at stride 4.
// ---------------------------------------------------------------------------
__global__ __launch_bounds__(128) void gemm2_kernel(
    const float* __restrict__ W2, int Nn) {
    __shared__ float xs[32][132];
    int t = threadIdx.x;
    int g = t >> 5;
    int c = t & 31;
    int n0 = blockIdx.x * 32;

    const float4* xv = (const float4*)g_x1;
    for (int i = t; i < 32 * 32; i += 128) {
        int m = i >> 5, cc = i & 31;
        int n = n0 + m;
        float4 v = (n < Nn) ? xv[(long long)n * 32 + cc]
                            : make_float4(0.f, 0.f, 0.f, 0.f);
        *(float4*)&xs[m][cc * 4] = v;
    }
    __syncthreads();

    unsigned long long acc[8];
#pragma unroll
    for (int m = 0; m < 8; m++) acc[m] = 0ull;

    for (int kt = 0; kt < C1; kt += 8) {
        float w[8];
#pragma unroll
        for (int j = 0; j < 8; j++) w[j] = W2[(kt + j) * HID + c];
        unsigned long long wp0, wp1, wp2, wp3;
        PACK2(wp0, w[0], w[1]);
        PACK2(wp1, w[2], w[3]);
        PACK2(wp2, w[4], w[5]);
        PACK2(wp3, w[6], w[7]);
#pragma unroll
        for (int m = 0; m < 8; m++) {
            const float4* xr = (const float4*)&xs[g * 8 + m][kt];
            float4 xa = xr[0], xb = xr[1];
            FMA2(acc[m], *(unsigned long long*)&xa.x, wp0);
            FMA2(acc[m], *(unsigned long long*)&xa.z, wp1);
            FMA2(acc[m], *(unsigned long long*)&xb.x, wp2);
            FMA2(acc[m], *(unsigned long long*)&xb.z, wp3);
        }
    }

#pragma unroll
    for (int m = 0; m < 8; m++) {
        float lo, hi;
        UNPACK2(lo, hi, acc[m]);
        float a = lo + hi;
        int n = n0 + g * 8 + m;
        if (n < Nn) g_h2h[(long long)n * HID + c] = __float2half_rn(a);
    }

    int mq = c >> 2, p = c & 3;
    int node = g * 8 + mq, gn2 = n0 + node;
    float s2 = 0.f, d2 = 0.f;
#pragma unroll
    for (int j = 0; j < 32; j++) {
        int k = p + j * 4;
        float xv2 = xs[node][k];
        s2 += xv2 * g_ws2[k];
        d2 += xv2 * g_wd2[k];
    }
    s2 += __shfl_xor_sync(0xffffffffu, s2, 1);
    s2 += __shfl_xor_sync(0xffffffffu, s2, 2);
    d2 += __shfl_xor_sync(0xffffffffu, d2, 1);
    d2 += __shfl_xor_sync(0xffffffffu, d2, 2);
    if (p == 0 && gn2 < Nn) { g_as2b[gn2 * 4] = s2; g_ad2[gn2] = d2; }
}

// ---------------------------------------------------------------------------
// Layer2 attention, STAGED (1 head: one exp per edge), scaled csr.
// ---------------------------------------------------------------------------
__global__ __launch_bounds__(256) void attn2_kernel(
    const float* __restrict__ b2, int Nn) {
    __shared__ __half2 s_al[8][32];
    __shared__ int     s_src[8][32];
    int wg   = threadIdx.x >> 5;
    int warp = (blockIdx.x * blockDim.x + threadIdx.x) >> 5;
    int lane = threadIdx.x & 31;
    if (warp >= Nn) return;
    int start = warp * DEGCAP;
    int deg   = g_cnt[warp];
    float adn = g_ad2[warp];
    int lane16 = lane & 15;
    int ep     = lane >> 4;

    float den = 0.f, ax = 0.f, ay = 0.f;
    const __half2* h2 = (const __half2*)g_h2h;
    const __half2 hz = __float2half2_rn(0.f);

#define A2_BODY(jj)                                                        \
    do {                                                                   \
        int ea = (jj) + ep, eb = (jj) + 2 + ep;                            \
        int sa = s_src[wg][ea], sb = s_src[wg][eb];                        \
        __half2 ala = s_al[wg][ea], alb = s_al[wg][eb];                    \
        t = __hfma2(h2[(sa << 2) + lane16], ala, t);                       \
        t = __hfma2(h2[(sb << 2) + lane16], alb, t);                       \
    } while (0)

    for (int base = 0; base < deg; base += 32) {
        int cnt = min(32, deg - base);
        int s4 = 0; float num = 0.f;
        if (lane < cnt) {
            s4 = g_csr[start + base + lane];
            num = __expf(lrelu(__ldg(&g_as2b[s4]) + adn));
            den += num;
        }
        s_src[wg][lane] = s4;
        s_al[wg][lane]  = __float2half2_rn(num);
        __syncwarp();

        int cnt4 = (cnt + 3) & ~3;
        int j = 0;
        for (; j + 8 <= cnt4; j += 8) {
            __half2 t = hz;
            A2_BODY(j);
            A2_BODY(j + 4);
            float2 q = __half22float2(t);
            ax += q.x; ay += q.y;
        }
        if (j < cnt4) {
            __half2 t = hz;
            A2_BODY(j);
            float2 q = __half22float2(t);
            ax += q.x; ay += q.y;
        }
        __syncwarp();
    }
#pragma unroll
    for (int off = 16; off; off >>= 1)
        den += __shfl_xor_sync(0xffffffffu, den, off);
    ax += __shfl_xor_sync(0xffffffffu, ax, 16);
    ay += __shfl_xor_sync(0xffffffffu, ay, 16);

    if (lane < 16) {
        float rden = 1.f / den;
        float2 bb = ((const float2*)b2)[lane16];
        float2 o;
        o.x = elu(ax * rden + bb.x);
        o.y = elu(ay * rden + bb.y);
        ((float2*)g_o2)[warp * 16 + lane16] = o;
    }
}

// ---------------------------------------------------------------------------
// Actor/critic heads.
// ---------------------------------------------------------------------------
__global__ __launch_bounds__(1024) void heads_kernel(
    const float* __restrict__ Wa, const float* __restrict__ ba,
    const float* __restrict__ Wc, const float* __restrict__ bc,
    float* __restrict__ out, int Nn) {
    __shared__ float Was[AGENTS * HID];
    __shared__ float tile[32][33];
    __shared__ float warr[32];
    int t = threadIdx.x;
    Was[t & (AGENTS * HID - 1)] = Wa[t & (AGENTS * HID - 1)];
    __syncthreads();

    int w = t >> 5, lane = t & 31;
    int n = blockIdx.x * 32 + w;
    float hv = (n < Nn) ? g_o2[(long long)n * HID + lane] : 0.f;

    float acc = 0.f;
    float vs = hv * Wc[lane];
#pragma unroll
    for (int f = 0; f < HID; f++) {
        float xv = __shfl_sync(0xffffffffu, hv, f);
        acc += xv * Was[f * AGENTS + lane];
    }
    tile[w][lane] = acc + ba[lane];
#pragma unroll
    for (int off = 16; off; off >>= 1) vs += __shfl_down_sync(0xffffffffu, vs, off);
    if (lane == 0) warr[w] = vs;
    __syncthreads();

    int n2 = blockIdx.x * 32 + lane;
    if (n2 < Nn) out[(long long)w * Nn + n2] = tile[lane][w];

    if (t == 0) {
        float bs = 0.f;
#pragma unroll
        for (int i = 0; i < 32; i++) bs += warr[i];
        atomicAdd(out + (long long)AGENTS * Nn, bs / (float)Nn);
        if (blockIdx.x == 0) atomicAdd(out + (long long)AGENTS * Nn, bc[0]);
    }
}

// ---------------------------------------------------------------------------
// Launch: fork-join streams — {prep, scatter} overlaps {cvt, gemm1}.
// Streams/events created once on the first (un-captured) correctness call;
// reused inside graph capture (standard fork-join capture pattern).
// ---------------------------------------------------------------------------
extern "C" void kernel_launch(void* const* d_in, const int* in_sizes, int n_in,
                              void* d_out, int out_size) {
    const float* x   = (const float*)d_in[0];
    const void*  ei  = d_in[1];
    const float* W1  = (const float*)d_in[2];
    const float* a1s = (const float*)d_in[3];
    const float* a1d = (const float*)d_in[4];
    const float* b1  = (const float*)d_in[5];
    const float* W2  = (const float*)d_in[6];
    const float* a2s = (const float*)d_in[7];
    const float* a2d = (const float*)d_in[8];
    const float* b2  = (const float*)d_in[9];
    const float* Wa  = (const float*)d_in[10];
    const float* ba  = (const float*)d_in[11];
    const float* Wc  = (const float*)d_in[12];
    const float* bc  = (const float*)d_in[13];
    float* out = (float*)d_out;

    int Nn   = in_sizes[0] / INDIM;
    int E    = in_sizes[1] / 2;
    int etot = E + Nn;
    int ncvt = INDIM * C1 + INDIM * 16 + 2 * INDIM;

    static cudaStream_t sB = nullptr;
    static cudaEvent_t  eF = nullptr, eJ = nullptr;
    if (sB == nullptr) {
        cudaStreamCreateWithFlags(&sB, cudaStreamNonBlocking);
        cudaEventCreateWithFlags(&eF, cudaEventDisableTiming);
        cudaEventCreateWithFlags(&eJ, cudaEventDisableTiming);
    }

    // fork: side stream gets the edge chain
    cudaEventRecord(eF, 0);
    cudaStreamWaitEvent(sB, eF, 0);
    prep_kernel<<<(Nn + 255) / 256, 256, 0, sB>>>((const unsigned int*)ei,
                                                  out, Nn);
    scatter_kernel<<<(etot + 1023) / 1024, 256, 0, sB>>>(ei, E, etot);
    cudaEventRecord(eJ, sB);

    // main stream: weight chain (concurrent with the edge chain)
    cvt_kernel<<<(ncvt + 255) / 256, 256>>>(W1, a1s, a1d, W2, a2s, a2d);
    gemm1_kernel<<<(Nn + 31) / 32, 288>>>(x, Nn);

    // join, then the serial tail
    cudaStreamWaitEvent(0, eJ, 0);
    attn1_kernel<<<(Nn * 32 + 255) / 256, 256>>>(b1, Nn);
    gemm2_kernel<<<(Nn + 31) / 32, 128>>>(W2, Nn);
    attn2_kernel<<<(Nn * 32 + 255) / 256, 256>>>(b2, Nn);
    heads_kernel<<<(Nn + 31) / 32, 1024>>>(Wa, ba, Wc, bc, out, Nn);
}

// round 17
// speedup vs baseline: 1.0383x; 1.0309x over previous
#include <cuda_runtime.h>
#include <cuda_fp16.h>
#include <mma.h>
#include <math.h>

using namespace nvcuda;

// ---------------------------------------------------------------------------
// Problem constants
// ---------------------------------------------------------------------------
#define MAXN   50000
#define DEGCAP 64
#define INDIM  128
#define HID    32
#define H1     4
#define C1     128
#define CW     144          // 128 h1 cols + 4 as + 4 ad + 8 pad
#define AGENTS 32
#define NEG    0.2f

// packed f32x2 ops (sm_103a)
#define FMA2(acc, a, b) \
    asm("fma.rn.f32x2 %0, %1, %2, %0;" : "+l"(acc) : "l"(a), "l"(b))
#define PACK2(out, lo, hi) \
    asm("mov.b64 %0, {%1, %2};" : "=l"(out) : "f"(lo), "f"(hi))
#define UNPACK2(lo, hi, in) \
    asm("mov.b64 {%0, %1}, %2;" : "=f"(lo), "=f"(hi) : "l"(in))

// ---------------------------------------------------------------------------
// Device scratch
// ---------------------------------------------------------------------------
__device__ __align__(16) __half g_h1h[MAXN * C1];   // layer1 feats (fp16)
__device__ __align__(16) __half g_Wch[INDIM * CW];  // W1|Ws|Wd fp16
__device__ __align__(16) float g_x1 [MAXN * C1];    // layer1 out (biased+elu)
__device__ __align__(16) float g_as1[MAXN * H1];
__device__ __align__(16) float g_ad1[MAXN * H1];
__device__ __align__(16) __half g_h2h[MAXN * HID];  // layer2 feats (fp16)
__device__ float g_ws2[INDIM];
__device__ float g_wd2[INDIM];
__device__ __align__(16) float g_as2b[MAXN * 4];    // as2 padded to stride 4
__device__ float g_ad2[MAXN];
__device__ int   g_cnt[MAXN];
__device__ int   g_csr[MAXN * DEGCAP];              // stores src*4 (scaled)
__device__ int   g_is64;

// ---------------------------------------------------------------------------
// Helpers
// ---------------------------------------------------------------------------
__device__ __forceinline__ float lrelu(float v) { return fmaxf(v, NEG * v); }
__device__ __forceinline__ float elu(float v)   { return v > 0.f ? v : expm1f(v); }

// ---------------------------------------------------------------------------
// prep+cvt fused: zero counters, probe dtype, zero value cell, build folded
// weights. One 196-block launch covers both index ranges.
// ---------------------------------------------------------------------------
__global__ void prep_cvt_kernel(const unsigned int* __restrict__ w,
                                const float* __restrict__ W1,
                                const float* __restrict__ a1s,
                                const float* __restrict__ a1d,
                                const float* __restrict__ W2,
                                const float* __restrict__ a2s,
                                const float* __restrict__ a2d,
                                float* __restrict__ out, int Nn) {
    int gid = blockIdx.x * blockDim.x + threadIdx.x;
    if (gid < Nn) g_cnt[gid] = 0;
    if (gid == 0) {
        out[(long long)AGENTS * Nn] = 0.f;
        int allz = 1;
        for (int k = 0; k < 16; k++)
            if (w[2 * k + 1] != 0u) allz = 0;
        g_is64 = allz;
    }
    if (gid < INDIM * C1) {
        int k = gid >> 7, c = gid & 127;
        g_Wch[k * CW + c] = __float2half_rn(W1[k * C1 + c]);
    } else if (gid < INDIM * C1 + INDIM * 16) {
        int i = gid - INDIM * C1;
        int k = i >> 4, cc = i & 15;
        float v = 0.f;
        if (cc < 4) {
            for (int j = 0; j < HID; j++)
                v += W1[k * C1 + cc * HID + j] * a1s[cc * HID + j];
        } else if (cc < 8) {
            int h = cc - 4;
            for (int j = 0; j < HID; j++)
                v += W1[k * C1 + h * HID + j] * a1d[h * HID + j];
        }
        g_Wch[k * CW + 128 + cc] = __float2half_rn(v);
    } else if (gid < INDIM * C1 + INDIM * 16 + 2 * INDIM) {
        int i = gid - INDIM * C1 - INDIM * 16;
        int k = i >> 1;
        const float* av = (i & 1) ? a2d : a2s;
        float v = 0.f;
        for (int j = 0; j < HID; j++) v += W2[k * HID + j] * av[j];
        if (i & 1) g_wd2[k] = v; else g_ws2[k] = v;
    }
}

// ---------------------------------------------------------------------------
// Scatter: padded-CSR bump allocation; 4 consecutive edges/thread,
// vectorized index loads; stores src*4 (scaled).
// ---------------------------------------------------------------------------
__global__ void scatter_kernel(const void* __restrict__ ei, int E, int etot) {
    int i0 = (blockIdx.x * blockDim.x + threadIdx.x) * 4;
    if (i0 >= etot) return;
    int s[4], d[4];
    if (g_is64) {
        const longlong2* ps = (const longlong2*)ei;
        const longlong2* pd = (const longlong2*)((const long long*)ei + E);
        if (i0 + 3 < E) {
            longlong2 a = ps[i0 >> 1], b = ps[(i0 >> 1) + 1];
            longlong2 c = pd[i0 >> 1], e2 = pd[(i0 >> 1) + 1];
            s[0] = (int)a.x; s[1] = (int)a.y; s[2] = (int)b.x; s[3] = (int)b.y;
            d[0] = (int)c.x; d[1] = (int)c.y; d[2] = (int)e2.x; d[3] = (int)e2.y;
        } else {
            const long long* q = (const long long*)ei;
#pragma unroll
            for (int k = 0; k < 4; k++) {
                int i = i0 + k;
                if (i < E) { s[k] = (int)q[i]; d[k] = (int)q[E + i]; }
                else       { s[k] = i - E;     d[k] = i - E; }
            }
        }
    } else {
        const int4* ps = (const int4*)ei;
        const int4* pd = (const int4*)((const int*)ei + E);
        if (i0 + 3 < E && (E & 3) == 0) {
            int4 a = ps[i0 >> 2], c = pd[i0 >> 2];
            s[0] = a.x; s[1] = a.y; s[2] = a.z; s[3] = a.w;
            d[0] = c.x; d[1] = c.y; d[2] = c.z; d[3] = c.w;
        } else {
            const int* q = (const int*)ei;
#pragma unroll
            for (int k = 0; k < 4; k++) {
                int i = i0 + k;
                if (i < E) { s[k] = q[i]; d[k] = q[E + i]; }
                else       { s[k] = i - E; d[k] = i - E; }
            }
        }
    }
#pragma unroll
    for (int k = 0; k < 4; k++) {
        int i = i0 + k;
        if (i < etot) {
            int pos = atomicAdd(&g_cnt[d[k]], 1);
            g_csr[d[k] * DEGCAP + pos] = s[k] * 4;
        }
    }
}

// ---------------------------------------------------------------------------
// GEMM1 tensor cores (proven 22.3us): [32 nodes] x [144 cols], 9 warps,
// B fragments loaded directly from global, folded as/ad cols.
// ---------------------------------------------------------------------------
__global__ __launch_bounds__(288) void gemm1_kernel(
    const float* __restrict__ x, int Nn) {
    __shared__ __half xh[32][136];
    __shared__ float  sbuf[32][148];
    int t  = threadIdx.x;
    int n0 = blockIdx.x * 32;

    const float4* xv = (const float4*)x;
    for (int i = t; i < 32 * 32; i += 288) {
        int m = i >> 5, c4 = i & 31;
        int n = n0 + m;
        float4 v = (n < Nn) ? xv[(long long)n * 32 + c4]
                            : make_float4(0.f, 0.f, 0.f, 0.f);
        __half2* dst = (__half2*)&xh[m][c4 * 4];
        dst[0] = __floats2half2_rn(v.x, v.y);
        dst[1] = __floats2half2_rn(v.z, v.w);
    }
    __syncthreads();

    int w = t >> 5;

    wmma::fragment<wmma::matrix_b, 16, 16, 16, __half, wmma::row_major> b[8];
#pragma unroll
    for (int k8 = 0; k8 < 8; k8++)
        wmma::load_matrix_sync(b[k8], g_Wch + (k8 * 16) * CW + w * 16, CW);

#pragma unroll
    for (int ng = 0; ng < 2; ng++) {
        wmma::fragment<wmma::accumulator, 16, 16, 16, float> cf;
        wmma::fill_fragment(cf, 0.f);
#pragma unroll
        for (int k8 = 0; k8 < 8; k8++) {
            wmma::fragment<wmma::matrix_a, 16, 16, 16, __half, wmma::row_major> a;
            wmma::load_matrix_sync(a, &xh[ng * 16][k8 * 16], 136);
            wmma::mma_sync(cf, a, b[k8], cf);
        }
        wmma::store_matrix_sync(&sbuf[ng * 16][w * 16], cf, 148,
                                wmma::mem_row_major);
    }
    __syncthreads();

    for (int i = t; i < 32 * 64; i += 288) {
        int n = i >> 6, cp = i & 63;
        int gn = n0 + n;
        if (gn < Nn) {
            __half2 hv = __floats2half2_rn(sbuf[n][cp * 2], sbuf[n][cp * 2 + 1]);
            ((__half2*)g_h1h)[(long long)gn * 64 + cp] = hv;
        }
    }
    if (t < 256) {
        int n = t >> 3, q = t & 7;
        int gn = n0 + n;
        if (gn < Nn) {
            if (q < 4) g_as1[gn * H1 + q]       = sbuf[n][128 + q];
            else       g_ad1[gn * H1 + (q - 4)] = sbuf[n][132 + (q - 4)];
        }
    }
}

// ---------------------------------------------------------------------------
// Layer1 attention, staging-free, scaled csr.
// ---------------------------------------------------------------------------
__global__ __launch_bounds__(256, 6) void attn1_kernel(
    const float* __restrict__ b1, int Nn) {
    int warp = (blockIdx.x * blockDim.x + threadIdx.x) >> 5;
    int lane = threadIdx.x & 31;
    if (warp >= Nn) return;
    int start = warp * DEGCAP;
    int deg   = g_cnt[warp];
    int lane16 = lane & 15;
    int ep     = lane >> 4;
    int hh     = lane16 >> 2;
    float adh  = g_ad1[warp * H1 + hh];

    float den = 0.f;
    float acc[8];
#pragma unroll
    for (int i = 0; i < 8; i++) acc[i] = 0.f;
    const uint4* h1 = (const uint4*)g_h1h;
    const __half2 hz = __float2half2_rn(0.f);

    for (int base = 0; base < deg; base += 8) {
        __half2 t0 = hz, t1 = hz, t2 = hz, t3 = hz;
#pragma unroll
        for (int jj = 0; jj < 8; jj += 2) {
            int e = base + jj + ep;
            bool ok = e < deg;
            int s4 = ok ? __ldg(&g_csr[start + e]) : 0;     // src*4
            float va = __ldg(&g_as1[s4 + hh]);
            float num = ok ? __expf(lrelu(va + adh)) : 0.f;
            den += num;
            __half2 nh = __float2half2_rn(num);
            uint4 u = h1[(s4 << 2) + lane16];
            t0 = __hfma2(*(__half2*)&u.x, nh, t0);
            t1 = __hfma2(*(__half2*)&u.y, nh, t1);
            t2 = __hfma2(*(__half2*)&u.z, nh, t2);
            t3 = __hfma2(*(__half2*)&u.w, nh, t3);
        }
        float2 q;
        q = __half22float2(t0); acc[0] += q.x; acc[1] += q.y;
        q = __half22float2(t1); acc[2] += q.x; acc[3] += q.y;
        q = __half22float2(t2); acc[4] += q.x; acc[5] += q.y;
        q = __half22float2(t3); acc[6] += q.x; acc[7] += q.y;
    }

    den += __shfl_xor_sync(0xffffffffu, den, 16);
#pragma unroll
    for (int i = 0; i < 8; i++)
        acc[i] += __shfl_xor_sync(0xffffffffu, acc[i], 16);

    if (lane < 16) {
        float rden = 1.f / den;
        const float4* bb = (const float4*)(b1 + lane16 * 8);
        float4 b0 = bb[0], b1v = bb[1];
        float4 o0, o1;
        o0.x = elu(acc[0] * rden + b0.x);  o0.y = elu(acc[1] * rden + b0.y);
        o0.z = elu(acc[2] * rden + b0.z);  o0.w = elu(acc[3] * rden + b0.w);
        o1.x = elu(acc[4] * rden + b1v.x); o1.y = elu(acc[5] * rden + b1v.y);
        o1.z = elu(acc[6] * rden + b1v.z); o1.w = elu(acc[7] * rden + b1v.w);
        float4* dst = (float4*)(g_x1 + (long long)warp * C1 + lane16 * 8);
        dst[0] = o0; dst[1] = o1;
    }
}

// ---------------------------------------------------------------------------
// GEMM2 (fp32 FFMA2) + folded as2/ad2; as2 written at stride 4.
// ---------------------------------------------------------------------------
__global__ __launch_bounds__(128) void gemm2_kernel(
    const float* __restrict__ W2, int Nn) {
    __shared__ float xs[32][132];
    int t = threadIdx.x;
    int g = t >> 5;
    int c = t & 31;
    int n0 = blockIdx.x * 32;

    const float4* xv = (const float4*)g_x1;
    for (int i = t; i < 32 * 32; i += 128) {
        int m = i >> 5, cc = i & 31;
        int n = n0 + m;
        float4 v = (n < Nn) ? xv[(long long)n * 32 + cc]
                            : make_float4(0.f, 0.f, 0.f, 0.f);
        *(float4*)&xs[m][cc * 4] = v;
    }
    __syncthreads();

    unsigned long long acc[8];
#pragma unroll
    for (int m = 0; m < 8; m++) acc[m] = 0ull;

    for (int kt = 0; kt < C1; kt += 8) {
        float w[8];
#pragma unroll
        for (int j = 0; j < 8; j++) w[j] = W2[(kt + j) * HID + c];
        unsigned long long wp0, wp1, wp2, wp3;
        PACK2(wp0, w[0], w[1]);
        PACK2(wp1, w[2], w[3]);
        PACK2(wp2, w[4], w[5]);
        PACK2(wp3, w[6], w[7]);
#pragma unroll
        for (int m = 0; m < 8; m++) {
            const float4* xr = (const float4*)&xs[g * 8 + m][kt];
            float4 xa = xr[0], xb = xr[1];
            FMA2(acc[m], *(unsigned long long*)&xa.x, wp0);
            FMA2(acc[m], *(unsigned long long*)&xa.z, wp1);
            FMA2(acc[m], *(unsigned long long*)&xb.x, wp2);
            FMA2(acc[m], *(unsigned long long*)&xb.z, wp3);
        }
    }

#pragma unroll
    for (int m = 0; m < 8; m++) {
        float lo, hi;
        UNPACK2(lo, hi, acc[m]);
        float a = lo + hi;
        int n = n0 + g * 8 + m;
        if (n < Nn) g_h2h[(long long)n * HID + c] = __float2half_rn(a);
    }

    int mq = c >> 2, p = c & 3;
    int node = g * 8 + mq, gn2 = n0 + node;
    float s2 = 0.f, d2 = 0.f;
#pragma unroll
    for (int j = 0; j < 32; j++) {
        int k = p + j * 4;
        float xv2 = xs[node][k];
        s2 += xv2 * g_ws2[k];
        d2 += xv2 * g_wd2[k];
    }
    s2 += __shfl_xor_sync(0xffffffffu, s2, 1);
    s2 += __shfl_xor_sync(0xffffffffu, s2, 2);
    d2 += __shfl_xor_sync(0xffffffffu, d2, 1);
    d2 += __shfl_xor_sync(0xffffffffu, d2, 2);
    if (p == 0 && gn2 < Nn) { g_as2b[gn2 * 4] = s2; g_ad2[gn2] = d2; }
}

// ---------------------------------------------------------------------------
// Layer2 attention FUSED with actor/critic heads.
// Phase A (per warp = 1 node): staged attention -> h vector -> smem tile.
// Phase B (block of 8 nodes): logits thread=(agent,node) + value dots.
// ---------------------------------------------------------------------------
__global__ __launch_bounds__(256) void attn2_heads_kernel(
    const float* __restrict__ b2, const float* __restrict__ Wa,
    const float* __restrict__ ba, const float* __restrict__ Wc,
    const float* __restrict__ bc, float* __restrict__ out, int Nn) {
    __shared__ __half2 s_al[8][32];
    __shared__ int     s_src[8][32];
    __shared__ float   tile[8][33];
    __shared__ float   Was[AGENTS * HID];      // 4 KB
    __shared__ float   warr[8];
    int t  = threadIdx.x;
    int wg = t >> 5, lane = t & 31;
    int node = blockIdx.x * 8 + wg;

    for (int i = t; i < AGENTS * HID; i += 256) Was[i] = Wa[i];

    if (node < Nn) {
        int start = node * DEGCAP;
        int deg   = g_cnt[node];
        float adn = g_ad2[node];
        int lane16 = lane & 15;
        int ep     = lane >> 4;

        float den = 0.f, ax = 0.f, ay = 0.f;
        const __half2* h2 = (const __half2*)g_h2h;
        const __half2 hz = __float2half2_rn(0.f);

#define A2_BODY(jj)                                                        \
        do {                                                               \
            int ea = (jj) + ep, eb = (jj) + 2 + ep;                        \
            int sa = s_src[wg][ea], sb = s_src[wg][eb];                    \
            __half2 ala = s_al[wg][ea], alb = s_al[wg][eb];                \
            tq = __hfma2(h2[(sa << 2) + lane16], ala, tq);                 \
            tq = __hfma2(h2[(sb << 2) + lane16], alb, tq);                 \
        } while (0)

        for (int base = 0; base < deg; base += 32) {
            int cnt = min(32, deg - base);
            int s4 = 0; float num = 0.f;
            if (lane < cnt) {
                s4 = g_csr[start + base + lane];
                num = __expf(lrelu(__ldg(&g_as2b[s4]) + adn));
                den += num;
            }
            s_src[wg][lane] = s4;
            s_al[wg][lane]  = __float2half2_rn(num);
            __syncwarp();

            int cnt4 = (cnt + 3) & ~3;
            int j = 0;
            for (; j + 8 <= cnt4; j += 8) {
                __half2 tq = hz;
                A2_BODY(j);
                A2_BODY(j + 4);
                float2 q = __half22float2(tq);
                ax += q.x; ay += q.y;
            }
            if (j < cnt4) {
                __half2 tq = hz;
                A2_BODY(j);
                float2 q = __half22float2(tq);
                ax += q.x; ay += q.y;
            }
            __syncwarp();
        }
#pragma unroll
        for (int off = 16; off; off >>= 1)
            den += __shfl_xor_sync(0xffffffffu, den, off);
        ax += __shfl_xor_sync(0xffffffffu, ax, 16);
        ay += __shfl_xor_sync(0xffffffffu, ay, 16);

        if (lane < 16) {
            float rden = 1.f / den;
            float2 bb = ((const float2*)b2)[lane16];
            tile[wg][lane16 * 2]     = elu(ax * rden + bb.x);
            tile[wg][lane16 * 2 + 1] = elu(ay * rden + bb.y);
        }
    } else if (lane < 32) {
        // keep tile defined for the value dot (guarded anyway)
        tile[wg][lane] = 0.f;
        if (lane == 0) tile[wg][32] = 0.f;
    }
    __syncthreads();

    // ---- logits: thread = (agent a, node nl) ----
    {
        int a  = t >> 3;            // 0..31
        int nl = t & 7;             // 0..7
        int n  = blockIdx.x * 8 + nl;
        float accv = ba[a];
#pragma unroll
        for (int f = 0; f < HID; f++)
            accv += tile[nl][f] * Was[f * AGENTS + a];
        if (n < Nn) out[(long long)a * Nn + n] = accv;
    }

    // ---- value: warp wg reduces its node ----
    {
        float hv = (node < Nn) ? tile[wg][lane] : 0.f;
        float vs = hv * Wc[lane];
#pragma unroll
        for (int off = 16; off; off >>= 1)
            vs += __shfl_down_sync(0xffffffffu, vs, off);
        if (lane == 0) warr[wg] = vs;
    }
    __syncthreads();
    if (t == 0) {
        float bs = warr[0] + warr[1] + warr[2] + warr[3]
                 + warr[4] + warr[5] + warr[6] + warr[7];
        atomicAdd(out + (long long)AGENTS * Nn, bs / (float)Nn);
        if (blockIdx.x == 0) atomicAdd(out + (long long)AGENTS * Nn, bc[0]);
    }
}

// ---------------------------------------------------------------------------
// Launch: single stream, 6 kernels; attn1 in the profiled 4th slot.
// ---------------------------------------------------------------------------
extern "C" void kernel_launch(void* const* d_in, const int* in_sizes, int n_in,
                              void* d_out, int out_size) {
    const float* x   = (const float*)d_in[0];
    const void*  ei  = d_in[1];
    const float* W1  = (const float*)d_in[2];
    const float* a1s = (const float*)d_in[3];
    const float* a1d = (const float*)d_in[4];
    const float* b1  = (const float*)d_in[5];
    const float* W2  = (const float*)d_in[6];
    const float* a2s = (const float*)d_in[7];
    const float* a2d = (const float*)d_in[8];
    const float* b2  = (const float*)d_in[9];
    const float* Wa  = (const float*)d_in[10];
    const float* ba  = (const float*)d_in[11];
    const float* Wc  = (const float*)d_in[12];
    const float* bc  = (const float*)d_in[13];
    float* out = (float*)d_out;

    int Nn   = in_sizes[0] / INDIM;
    int E    = in_sizes[1] / 2;
    int etot = E + Nn;

    prep_cvt_kernel<<<(Nn + 255) / 256, 256>>>((const unsigned int*)ei,
                                               W1, a1s, a1d, W2, a2s, a2d,
                                               out, Nn);
    scatter_kernel<<<(etot + 1023) / 1024, 256>>>(ei, E, etot);
    gemm1_kernel<<<(Nn + 31) / 32, 288>>>(x, Nn);
    attn1_kernel<<<(Nn * 32 + 255) / 256, 256>>>(b1, Nn);   // 4th: profiled

    gemm2_kernel<<<(Nn + 31) / 32, 128>>>(W2, Nn);
    attn2_heads_kernel<<<(Nn + 7) / 8, 256>>>(b2, Wa, ba, Wc, bc, out, Nn);
}